// round 7
// baseline (speedup 1.0000x reference)
#include <cuda_runtime.h>
#include <cstdint>

// Linear_60876866453656: out[n, off+w*d+i] = 0.125 * sum_u x[n, off+u*d+i] * W_l[u,w]
// N=262144 rows x 576 f32.
// Round 7 = Round 6 resubmit (infra failure, kernel unexercised).
// Swizzle fix vs round 5: quad XOR masks the ROW, preserving quad bit 3
// (old code aliased u>=32 onto u<32).
// Design: l-specialized CTAs (bid%9 -> 1:3:5), 256 thr/CTA, 64-reg cap,
// 4 CTAs/SM (32 warps). XOR-swizzled padding-free x buffers, weights smem
// broadcast, f32x2 FMA, l2 split into 2 i-passes with smem stash of partials.

static constexpr int THREADS = 256;
static constexpr int W_WORDS = 4096;                 // 64x64 weights per class
static constexpr int XB_WORDS = 32 * 320;            // max xbuf (l2)
static constexpr int SMEM_BYTES = (W_WORDS + XB_WORDS) * 4;   // 57344

__device__ __forceinline__ void fma2(unsigned long long& d,
                                     unsigned long long a,
                                     unsigned long long b) {
    asm("fma.rn.f32x2 %0, %1, %2, %0;" : "+l"(d) : "l"(a), "l"(b));
}
__device__ __forceinline__ float hadd2(unsigned long long v) {
    float2 f = *reinterpret_cast<float2*>(&v);
    return f.x + f.y;
}

// xbuf word index for (row, i, u): XOR swizzle, no padding.
// quad = (u>>2) ^ (row&7)  -- XOR only flips the low 3 quad bits, preserving
// quad bit 3, so the mapping is bijective in u and conflict-free across the
// 8 rows of an LDS.128 wavefront phase.
template<int D>
__device__ __forceinline__ int xaddr(int row, int i, int u) {
    return row * (64 * D) + i * 64 + (((u >> 2) ^ (row & 7)) << 2) + (u & 3);
}

// Coalesced LDG of one l-block + transposed swizzled STS.
template<int D, int OFF, int CH>
__device__ __forceinline__ void load_chunk(const float* __restrict__ x,
                                           float* __restrict__ xb,
                                           int row0, int tid) {
    constexpr int ITER = CH * D / 16;
#pragma unroll
    for (int k = 0; k < ITER; k++) {
        int q   = tid + THREADS * k;
        int row = q / (16 * D);
        int c4  = q % (16 * D);
        float4 v = *reinterpret_cast<const float4*>(
            x + (size_t)(row0 + row) * 576 + OFF + 4 * c4);
        const float* pf = reinterpret_cast<const float*>(&v);
#pragma unroll
        for (int e = 0; e < 4; e++) {
            int p = 4 * c4 + e;                      // p = u*D + i
            xb[xaddr<D>(row, p % D, p / D)] = pf[e];
        }
    }
}

// One compute pass over planes [I0, I0+NI): 8 w-cols, one row (=lane).
template<int D, int NI, int I0>
__device__ __forceinline__ void compute_pass(const float* __restrict__ xb,
                                             const float* __restrict__ wsm,
                                             int row, int w0, float (&res)[8 * NI]) {
    unsigned long long acc[8][NI];
#pragma unroll
    for (int j = 0; j < 8; j++)
#pragma unroll
        for (int i = 0; i < NI; i++) acc[j][i] = 0ull;

    const float* __restrict__ xr = xb + row * (64 * D);
    const int sw = (row & 7) << 2;
#pragma unroll 4
    for (int g = 0; g < 16; g++) {
        int xo = (g << 2) ^ sw;                      // == ((g ^ (row&7)) << 2)
        ulonglong2 xv[NI];
#pragma unroll
        for (int i = 0; i < NI; i++)
            xv[i] = *reinterpret_cast<const ulonglong2*>(xr + (I0 + i) * 64 + xo);
#pragma unroll
        for (int j = 0; j < 8; j++) {
            ulonglong2 wv = *reinterpret_cast<const ulonglong2*>(
                wsm + (w0 + j) * 64 + 4 * g);        // uniform broadcast
#pragma unroll
            for (int i = 0; i < NI; i++) {
                fma2(acc[j][i], xv[i].x, wv.x);
                fma2(acc[j][i], xv[i].y, wv.y);
            }
        }
    }
#pragma unroll
    for (int j = 0; j < 8; j++)
#pragma unroll
        for (int i = 0; i < NI; i++) res[j * NI + i] = hadd2(acc[j][i]);
}

__device__ __forceinline__ void stg4(float* p, const float* r) {
    *reinterpret_cast<float4*>(p) = make_float4(r[0], r[1], r[2], r[3]);
}

__global__ __launch_bounds__(THREADS, 4)
void lin_kernel(const float* __restrict__ x,
                const float* __restrict__ w0g,
                const float* __restrict__ w1g,
                const float* __restrict__ w2g,
                float* __restrict__ out) {
    extern __shared__ float sm[];
    float* wsm = sm;
    float* xb  = sm + W_WORDS;

    const int tid  = threadIdx.x;
    const int lane = tid & 31;
    const int wid  = tid >> 5;
    const int w0   = wid * 8;

    // ---- class dispatch: bid%9 -> 0:l0, 1-3:l1, 4-8:l2 ----
    const int bid = blockIdx.x, G = gridDim.x;
    const int r9 = bid % 9, n9 = bid / 9;
    int cls, base, kk;
    if (r9 == 0)      { cls = 0; base = 0; kk = 1; }
    else if (r9 <= 3) { cls = 1; base = 1; kk = 3; }
    else              { cls = 2; base = 4; kk = 5; }
    const int rank = n9 * kk + (r9 - base);
    const int full = G / 9, rem = G % 9;
    int extra = rem - base; if (extra < 0) extra = 0; if (extra > kk) extra = kk;
    const int cnt = full * kk + extra;

    // ---- weights -> smem [w][u], 0.125 folded ----
    const float* wsrc = (cls == 0) ? w0g : (cls == 1) ? w1g : w2g;
    for (int idx = tid; idx < W_WORDS; idx += THREADS) {
        int u = idx >> 6, w = idx & 63;
        wsm[w * 64 + u] = 0.125f * wsrc[idx];
    }
    __syncthreads();

    if (cls == 0) {
        // ======== l=0 : D=1, OFF=0, CH=64, 2 rows per lane ========
        const int nch = 262144 / 64;
        for (int c = rank; c < nch; c += cnt) {
            const int row0 = c * 64;
            load_chunk<1, 0, 64>(x, xb, row0, tid);
            __syncthreads();

            const int ra = lane, rb = lane + 32;
            unsigned long long a0[8], a1[8];
#pragma unroll
            for (int j = 0; j < 8; j++) { a0[j] = 0ull; a1[j] = 0ull; }
            const float* xr0 = xb + ra * 64;
            const float* xr1 = xb + rb * 64;
            const int s0 = (ra & 7) << 2, s1 = (rb & 7) << 2;
#pragma unroll 4
            for (int g = 0; g < 16; g++) {
                ulonglong2 xv0 = *reinterpret_cast<const ulonglong2*>(xr0 + ((g << 2) ^ s0));
                ulonglong2 xv1 = *reinterpret_cast<const ulonglong2*>(xr1 + ((g << 2) ^ s1));
#pragma unroll
                for (int j = 0; j < 8; j++) {
                    ulonglong2 wv = *reinterpret_cast<const ulonglong2*>(
                        wsm + (w0 + j) * 64 + 4 * g);
                    fma2(a0[j], xv0.x, wv.x); fma2(a0[j], xv0.y, wv.y);
                    fma2(a1[j], xv1.x, wv.x); fma2(a1[j], xv1.y, wv.y);
                }
            }
            float r0f[8], r1f[8];
#pragma unroll
            for (int j = 0; j < 8; j++) { r0f[j] = hadd2(a0[j]); r1f[j] = hadd2(a1[j]); }
            float* oa = out + (size_t)(row0 + ra) * 576 + w0;
            float* ob = out + (size_t)(row0 + rb) * 576 + w0;
            stg4(oa, r0f); stg4(oa + 4, r0f + 4);
            stg4(ob, r1f); stg4(ob + 4, r1f + 4);
            __syncthreads();
        }
    } else if (cls == 1) {
        // ======== l=1 : D=3, OFF=64, CH=32 ========
        const int nch = 262144 / 32;
        for (int c = rank; c < nch; c += cnt) {
            const int row0 = c * 32;
            load_chunk<3, 64, 32>(x, xb, row0, tid);
            __syncthreads();

            float res[24];
            compute_pass<3, 3, 0>(xb, wsm, lane, w0, res);
            float* ob = out + (size_t)(row0 + lane) * 576 + 64 + w0 * 3;
#pragma unroll
            for (int v = 0; v < 6; v++) stg4(ob + 4 * v, res + 4 * v);
            __syncthreads();
        }
    } else {
        // ======== l=2 : D=5, OFF=256, CH=32, 2 i-passes + smem stash ========
        const int nch = 262144 / 32;
        // per-thread stash slot inside planes {0,1} region: 16 floats
        float* stash = xb + (tid >> 3) * 320 + (tid & 7) * 16;
        for (int c = rank; c < nch; c += cnt) {
            const int row0 = c * 32;
            load_chunk<5, 256, 32>(x, xb, row0, tid);
            __syncthreads();

            float resA[16];
            compute_pass<5, 2, 0>(xb, wsm, lane, w0, resA);   // planes 0,1
            __syncthreads();                                   // all done w/ planes 0,1
#pragma unroll
            for (int v = 0; v < 4; v++)
                *reinterpret_cast<float4*>(stash + 4 * v) =
                    make_float4(resA[4*v], resA[4*v+1], resA[4*v+2], resA[4*v+3]);

            float resB[24];
            compute_pass<5, 3, 2>(xb, wsm, lane, w0, resB);   // planes 2,3,4

            float res[40];
#pragma unroll
            for (int j = 0; j < 8; j++) {
                res[j * 5 + 0] = stash[j * 2 + 0];
                res[j * 5 + 1] = stash[j * 2 + 1];
                res[j * 5 + 2] = resB[j * 3 + 0];
                res[j * 5 + 3] = resB[j * 3 + 1];
                res[j * 5 + 4] = resB[j * 3 + 2];
            }
            float* ob = out + (size_t)(row0 + lane) * 576 + 256 + w0 * 5;
#pragma unroll
            for (int v = 0; v < 10; v++) stg4(ob + 4 * v, res + 4 * v);
            __syncthreads();
        }
    }
}

extern "C" void kernel_launch(void* const* d_in, const int* in_sizes, int n_in,
                              void* d_out, int out_size) {
    const float* x  = (const float*)d_in[0];
    const float* w0 = (const float*)d_in[1];
    const float* w1 = (const float*)d_in[2];
    const float* w2 = (const float*)d_in[3];
    float* out = (float*)d_out;

    cudaFuncSetAttribute(lin_kernel,
                         cudaFuncAttributeMaxDynamicSharedMemorySize, SMEM_BYTES);
    lin_kernel<<<592, THREADS, SMEM_BYTES>>>(x, w0, w1, w2, out);  // 4 CTAs/SM
}

// round 9
// speedup vs baseline: 1.1044x; 1.1044x over previous
#include <cuda_runtime.h>
#include <cstdint>

// Linear_60876866453656: out[n, off+w*d+i] = 0.125 * sum_u x[n, off+u*d+i] * W_l[u,w]
// N=262144 rows x 576 f32.
// Round 9 = Round 8 with load_chunk trip-count fix (ITER = CH*D/16, was /8:
// doubled loop -> OOB global reads + smem overflow -> illegal memory access).
// Design: class-specialized CTAs (bid%9 -> 1:3:5), 256 thr / 8 warps,
// warp owns 8 w-cols, single-pass accumulation (acc 8w x D), double-buffered
// x chunks with ONE sync per chunk, 2 CTAs/SM.

static constexpr int THREADS = 256;           // 8 warps
static constexpr int CH      = 32;            // rows per chunk (= lanes)
static constexpr int W_WORDS = 4096;          // 64x64 weights per class
static constexpr int XBUF    = CH * 320;      // max per-buffer words (l2: 32*64*5)
static constexpr int SMEM_BYTES = (W_WORDS + 2 * XBUF) * 4;   // 98304

__device__ __forceinline__ void fma2(unsigned long long& d,
                                     unsigned long long a,
                                     unsigned long long b) {
    asm("fma.rn.f32x2 %0, %1, %2, %0;" : "+l"(d) : "l"(a), "l"(b));
}
__device__ __forceinline__ float hadd2(unsigned long long v) {
    float2 f = *reinterpret_cast<float2*>(&v);
    return f.x + f.y;
}

// xbuf word index for (row, i, u): XOR swizzle, no padding.
// quad = (u>>2) ^ (row&7): flips only low 3 quad bits (bijective in u),
// conflict-free across the 8 rows of an LDS.128 wavefront phase.
template<int D>
__device__ __forceinline__ int xaddr(int row, int i, int u) {
    return row * (64 * D) + i * 64 + (((u >> 2) ^ (row & 7)) << 2) + (u & 3);
}

// Coalesced LDG of one l-block + transposed swizzled STS.
template<int D, int OFF>
__device__ __forceinline__ void load_chunk(const float* __restrict__ x,
                                           float* __restrict__ xb,
                                           int row0, int tid) {
    constexpr int ITER = CH * D / 16;         // float4s per thread = 2*D
#pragma unroll
    for (int k = 0; k < ITER; k++) {
        int q   = tid + THREADS * k;
        int row = q / (16 * D);
        int c4  = q % (16 * D);
        float4 v = *reinterpret_cast<const float4*>(
            x + (size_t)(row0 + row) * 576 + OFF + 4 * c4);
        const float* pf = reinterpret_cast<const float*>(&v);
#pragma unroll
        for (int e = 0; e < 4; e++) {
            int p = 4 * c4 + e;                      // p = u*D + i
            xb[xaddr<D>(row, p % D, p / D)] = pf[e];
        }
    }
}

// Single-pass compute: all D planes, 8 w-cols, row = lane.
template<int D, int OFF>
__device__ __forceinline__ void do_compute(const float* __restrict__ xb,
                                           const float* __restrict__ wsm,
                                           float* __restrict__ out,
                                           int row0, int lane, int w0) {
    unsigned long long acc[8][D];
#pragma unroll
    for (int j = 0; j < 8; j++)
#pragma unroll
        for (int i = 0; i < D; i++) acc[j][i] = 0ull;

    const float* __restrict__ xr = xb + lane * (64 * D);
    const int sw = (lane & 7) << 2;
#pragma unroll 4
    for (int g = 0; g < 16; g++) {                   // 4 u's per g
        int xo = (g << 2) ^ sw;
        ulonglong2 xv[D];
#pragma unroll
        for (int i = 0; i < D; i++)
            xv[i] = *reinterpret_cast<const ulonglong2*>(xr + i * 64 + xo);
#pragma unroll
        for (int j = 0; j < 8; j++) {
            ulonglong2 wv = *reinterpret_cast<const ulonglong2*>(
                wsm + (w0 + j) * 64 + 4 * g);        // uniform broadcast
#pragma unroll
            for (int i = 0; i < D; i++) {
                fma2(acc[j][i], xv[i].x, wv.x);
                fma2(acc[j][i], xv[i].y, wv.y);
            }
        }
    }

    // Thread owns out[row, OFF + w0*D .. +8D) -- contiguous STG.128.
    float res[8 * D];
#pragma unroll
    for (int j = 0; j < 8; j++)
#pragma unroll
        for (int i = 0; i < D; i++) res[j * D + i] = hadd2(acc[j][i]);

    float* __restrict__ ob = out + (size_t)(row0 + lane) * 576 + OFF + w0 * D;
#pragma unroll
    for (int v = 0; v < 2 * D; v++)
        *reinterpret_cast<float4*>(ob + 4 * v) =
            make_float4(res[4*v], res[4*v+1], res[4*v+2], res[4*v+3]);
}

// Per-class driver: double-buffered chunk pipeline, one sync per chunk.
template<int D, int OFF>
__device__ __forceinline__ void run_class(const float* __restrict__ x,
                                          const float* __restrict__ wsm,
                                          float* __restrict__ xb0,
                                          float* __restrict__ xb1,
                                          float* __restrict__ out,
                                          int rank, int cnt, int tid,
                                          int lane, int w0) {
    const int nch = 262144 / CH;                     // 8192
    int c = rank;
    if (c >= nch) { return; }

    load_chunk<D, OFF>(x, xb0, c * CH, tid);
    __syncthreads();

    float* bufs[2] = {xb0, xb1};
    int p = 0;
    while (true) {
        int cn = c + cnt;
        if (cn < nch)
            load_chunk<D, OFF>(x, bufs[p ^ 1], cn * CH, tid);
        do_compute<D, OFF>(bufs[p], wsm, out, c * CH, lane, w0);
        __syncthreads();
        if (cn >= nch) break;
        c = cn;
        p ^= 1;
    }
}

__global__ __launch_bounds__(THREADS, 2)
void lin_kernel(const float* __restrict__ x,
                const float* __restrict__ w0g,
                const float* __restrict__ w1g,
                const float* __restrict__ w2g,
                float* __restrict__ out) {
    extern __shared__ float sm[];
    float* wsm = sm;
    float* xb0 = sm + W_WORDS;
    float* xb1 = sm + W_WORDS + XBUF;

    const int tid  = threadIdx.x;
    const int lane = tid & 31;
    const int wid  = tid >> 5;
    const int w0   = wid * 8;                        // 8 warps x 8 = 64 w-cols

    // ---- class dispatch: bid%9 -> 0:l0, 1-3:l1, 4-8:l2 ----
    const int bid = blockIdx.x, G = gridDim.x;
    const int r9 = bid % 9, n9 = bid / 9;
    int cls, base, kk;
    if (r9 == 0)      { cls = 0; base = 0; kk = 1; }
    else if (r9 <= 3) { cls = 1; base = 1; kk = 3; }
    else              { cls = 2; base = 4; kk = 5; }
    const int rank = n9 * kk + (r9 - base);
    const int full = G / 9, rem = G % 9;
    int extra = rem - base; if (extra < 0) extra = 0; if (extra > kk) extra = kk;
    const int cnt = full * kk + extra;

    // ---- weights -> smem [w][u], 0.125 folded ----
    const float* wsrc = (cls == 0) ? w0g : (cls == 1) ? w1g : w2g;
    for (int idx = tid; idx < W_WORDS; idx += THREADS) {
        int u = idx >> 6, w = idx & 63;
        wsm[w * 64 + u] = 0.125f * wsrc[idx];
    }
    __syncthreads();

    if (cls == 0)
        run_class<1, 0>(x, wsm, xb0, xb1, out, rank, cnt, tid, lane, w0);
    else if (cls == 1)
        run_class<3, 64>(x, wsm, xb0, xb1, out, rank, cnt, tid, lane, w0);
    else
        run_class<5, 256>(x, wsm, xb0, xb1, out, rank, cnt, tid, lane, w0);
}

extern "C" void kernel_launch(void* const* d_in, const int* in_sizes, int n_in,
                              void* d_out, int out_size) {
    const float* x  = (const float*)d_in[0];
    const float* w0 = (const float*)d_in[1];
    const float* w1 = (const float*)d_in[2];
    const float* w2 = (const float*)d_in[3];
    float* out = (float*)d_out;

    cudaFuncSetAttribute(lin_kernel,
                         cudaFuncAttributeMaxDynamicSharedMemorySize, SMEM_BYTES);
    lin_kernel<<<296, THREADS, SMEM_BYTES>>>(x, w0, w1, w2, out);  // 2 CTAs/SM
}